// round 1
// baseline (speedup 1.0000x reference)
#include <cuda_runtime.h>
#include <math.h>

#define DIM 768
#define NHEAD 16
#define HD 48
#define SEQ 2048
#define ATTN_SCALE 0.14433756729740643f  // 1/sqrt(48)

// ---------------------------------------------------------------------------
// Scratch (device globals: allocation-guard-safe)
// ---------------------------------------------------------------------------
__device__ float g_q[8192 * DIM];
__device__ float g_k[8192 * DIM];
__device__ float g_v[8192 * DIM];
__device__ float g_ao[8192 * DIM];

// ---------------------------------------------------------------------------
// SGEMM: C[m][n] = sum_k A[m][k] * W[n][k] + bias[n]
// (torch Linear: y = x @ W^T + b). A:[M,K] row-major, W:[N,K] row-major.
// 128x128 block tile, BK=16, 256 threads, 8x8 per-thread microtile.
// ---------------------------------------------------------------------------
__global__ __launch_bounds__(256) void gemm_nt_bias(
    const float* __restrict__ A, const float* __restrict__ W,
    const float* __restrict__ bias, float* __restrict__ C,
    int M, int N, int K)
{
    __shared__ __align__(16) float As[16][132];  // padded: row stride 528B (16B-mult)
    __shared__ __align__(16) float Ws[16][132];

    const int tid = threadIdx.x;
    const int bm = blockIdx.y * 128;
    const int bn = blockIdx.x * 128;
    const int tx = tid & 15;    // 0..15 -> N
    const int ty = tid >> 4;    // 0..15 -> M

    float acc[8][8];
#pragma unroll
    for (int i = 0; i < 8; i++)
#pragma unroll
        for (int j = 0; j < 8; j++) acc[i][j] = 0.f;

    for (int k0 = 0; k0 < K; k0 += 16) {
#pragma unroll
        for (int it = 0; it < 2; it++) {
            int idx = tid + it * 256;       // 0..511
            int row = idx >> 2;             // 0..127
            int c4  = (idx & 3) * 4;        // 0,4,8,12
            float4 a = *(const float4*)(A + (size_t)(bm + row) * K + k0 + c4);
            As[c4 + 0][row] = a.x; As[c4 + 1][row] = a.y;
            As[c4 + 2][row] = a.z; As[c4 + 3][row] = a.w;
            float4 w = *(const float4*)(W + (size_t)(bn + row) * K + k0 + c4);
            Ws[c4 + 0][row] = w.x; Ws[c4 + 1][row] = w.y;
            Ws[c4 + 2][row] = w.z; Ws[c4 + 3][row] = w.w;
        }
        __syncthreads();

#pragma unroll
        for (int k = 0; k < 16; k++) {
            float a[8], b[8];
            *(float4*)(a)     = *(const float4*)&As[k][ty * 8];
            *(float4*)(a + 4) = *(const float4*)&As[k][ty * 8 + 4];
            *(float4*)(b)     = *(const float4*)&Ws[k][tx * 8];
            *(float4*)(b + 4) = *(const float4*)&Ws[k][tx * 8 + 4];
#pragma unroll
            for (int i = 0; i < 8; i++)
#pragma unroll
                for (int j = 0; j < 8; j++)
                    acc[i][j] += a[i] * b[j];
        }
        __syncthreads();
    }

    // epilogue: add bias, vectorized store
#pragma unroll
    for (int i = 0; i < 8; i++) {
        int row = bm + ty * 8 + i;
#pragma unroll
        for (int j = 0; j < 8; j += 4) {
            int col = bn + tx * 8 + j;
            float4 bb = *(const float4*)(bias + col);
            float4 o;
            o.x = acc[i][j + 0] + bb.x;
            o.y = acc[i][j + 1] + bb.y;
            o.z = acc[i][j + 2] + bb.z;
            o.w = acc[i][j + 3] + bb.w;
            *(float4*)(C + (size_t)row * N + col) = o;
        }
    }
}

// ---------------------------------------------------------------------------
// Flash attention: one thread = one query row. Q/K/V laid out [B*S, DIM],
// head h occupies cols [h*48, h*48+48). KV staged in shared, 32 rows/tile,
// online softmax with a single rescale per tile.
// grid: (S/128, NHEAD, B), block: 128
// ---------------------------------------------------------------------------
__global__ __launch_bounds__(128) void flash_attn(
    const float* __restrict__ Q, const float* __restrict__ K,
    const float* __restrict__ V, float* __restrict__ O)
{
    __shared__ __align__(16) float Ks[32][48];
    __shared__ __align__(16) float Vs[32][48];

    const int t  = threadIdx.x;
    const int h  = blockIdx.y;
    const int b  = blockIdx.z;
    const int qi = blockIdx.x * 128 + t;

    const float* qp = Q + ((size_t)(b * SEQ + qi)) * DIM + h * HD;
    float q[48];
#pragma unroll
    for (int d = 0; d < 48; d += 4) {
        float4 f = *(const float4*)(qp + d);
        q[d + 0] = f.x * ATTN_SCALE; q[d + 1] = f.y * ATTN_SCALE;
        q[d + 2] = f.z * ATTN_SCALE; q[d + 3] = f.w * ATTN_SCALE;
    }

    float o[48];
#pragma unroll
    for (int d = 0; d < 48; d++) o[d] = 0.f;
    float m = -1e30f, l = 0.f;

    const float* Kb = K + (size_t)b * SEQ * DIM + h * HD;
    const float* Vb = V + (size_t)b * SEQ * DIM + h * HD;

    for (int kv0 = 0; kv0 < SEQ; kv0 += 32) {
        // cooperative tile load: 32 rows x 12 float4 = 384 float4 per tensor
#pragma unroll
        for (int i = 0; i < 3; i++) {
            int idx = t + i * 128;
            int row = idx / 12;
            int c4  = (idx % 12) * 4;
            *(float4*)&Ks[row][c4] = *(const float4*)(Kb + (size_t)(kv0 + row) * DIM + c4);
            *(float4*)&Vs[row][c4] = *(const float4*)(Vb + (size_t)(kv0 + row) * DIM + c4);
        }
        __syncthreads();

        float s[32];
        float mt = m;
#pragma unroll 4
        for (int j = 0; j < 32; j++) {
            const float4* kr = (const float4*)Ks[j];
            float a0 = 0.f, a1 = 0.f, a2 = 0.f, a3 = 0.f;
#pragma unroll
            for (int dd = 0; dd < 12; dd++) {
                float4 kk = kr[dd];
                a0 += q[dd * 4 + 0] * kk.x;
                a1 += q[dd * 4 + 1] * kk.y;
                a2 += q[dd * 4 + 2] * kk.z;
                a3 += q[dd * 4 + 3] * kk.w;
            }
            float acc = (a0 + a1) + (a2 + a3);
            s[j] = acc;
            mt = fmaxf(mt, acc);
        }

        float corr = __expf(m - mt);
        m = mt;
        l *= corr;
#pragma unroll
        for (int d = 0; d < 48; d++) o[d] *= corr;

#pragma unroll 4
        for (int j = 0; j < 32; j++) {
            float p = __expf(s[j] - m);
            l += p;
            const float4* vr = (const float4*)Vs[j];
#pragma unroll
            for (int dd = 0; dd < 12; dd++) {
                float4 vv = vr[dd];
                o[dd * 4 + 0] += p * vv.x;
                o[dd * 4 + 1] += p * vv.y;
                o[dd * 4 + 2] += p * vv.z;
                o[dd * 4 + 3] += p * vv.w;
            }
        }
        __syncthreads();
    }

    const float inv = 1.f / l;
    float* op = O + ((size_t)(b * SEQ + qi)) * DIM + h * HD;
#pragma unroll
    for (int d = 0; d < 48; d += 4) {
        float4 f;
        f.x = o[d + 0] * inv; f.y = o[d + 1] * inv;
        f.z = o[d + 2] * inv; f.w = o[d + 3] * inv;
        *(float4*)(op + d) = f;
    }
}

// ---------------------------------------------------------------------------
// launch
// ---------------------------------------------------------------------------
extern "C" void kernel_launch(void* const* d_in, const int* in_sizes, int n_in,
                              void* d_out, int out_size)
{
    const float* x  = (const float*)d_in[0];
    const float* Wq = (const float*)d_in[1];
    const float* bq = (const float*)d_in[2];
    const float* Wk = (const float*)d_in[3];
    const float* bk = (const float*)d_in[4];
    const float* Wv = (const float*)d_in[5];
    const float* bv = (const float*)d_in[6];
    const float* Wo = (const float*)d_in[7];
    const float* bo = (const float*)d_in[8];
    float* out = (float*)d_out;

    const int M = in_sizes[0] / DIM;   // B*S = 8192
    const int B = M / SEQ;             // 4

    float *qp, *kp, *vp, *aop;
    cudaGetSymbolAddress((void**)&qp,  g_q);
    cudaGetSymbolAddress((void**)&kp,  g_k);
    cudaGetSymbolAddress((void**)&vp,  g_v);
    cudaGetSymbolAddress((void**)&aop, g_ao);

    dim3 ggrid(DIM / 128, M / 128);    // (6, 64)
    gemm_nt_bias<<<ggrid, 256>>>(x, Wq, bq, qp, M, DIM, DIM);
    gemm_nt_bias<<<ggrid, 256>>>(x, Wk, bk, kp, M, DIM, DIM);
    gemm_nt_bias<<<ggrid, 256>>>(x, Wv, bv, vp, M, DIM, DIM);

    dim3 agrid(SEQ / 128, NHEAD, B);   // (16, 16, 4)
    flash_attn<<<agrid, 128>>>(qp, kp, vp, aop);

    gemm_nt_bias<<<ggrid, 256>>>(aop, Wo, bo, out, M, DIM, DIM);
}